// round 12
// baseline (speedup 1.0000x reference)
#include <cuda_runtime.h>
#include <cuda_fp16.h>
#include <cstdint>
#include <cstddef>

// out = x @ Wv^T + bv.  (Reference's softmax rows sum to 1 => its final
// einsum('btu,btj->btj', weights, v) == v + rounding; Q/K/softmax are dead.)
//
// Single-pass fp16 GEMM M=8192, K=1024, N=64 on portable mma.sync m16n8k16:
//   D = f16(x)*f16(W), fp32 accumulate; rel_err 2.92e-4 (measured) < 1e-3.
// R12: decouple SM occupancy from one mega-CTA. 256 CTAs (M-tile 32) x 256
// threads (8 warps = 2M x 2N x 2K-split). W streams from L2-hot g_wf via a
// 3-stage cp.async ring (no 131KB resident prologue). Smem 72KB -> 2 CTAs/SM
// in independent barrier domains.

#define NEMB    1024
#define NH      64
#define MT      32
#define THREADS 256
#define GRID    256             // 8192 / 32
#define KCH     128             // K per chunk
#define NCH     8
#define PW      24              // words per row per k32 sub-block
#define SUBW    (MT * PW + 8)   // 776 words per sub-block (pad vs STS conflicts)
#define XBUFW   (4 * SUBW)      // 3104 words per x buffer
#define WST_U4  1024            // uint4 per W stage (8 steps * 128)
#define WSM_BYTES (3 * WST_U4 * 16)          // 49152
#define XSM_BYTES (2 * XBUFW * 4)            // 24832
#define SMEM_BYTES (WSM_BYTES + XSM_BYTES)   // 73984

static_assert(SMEM_BYTES <= 227328, "fits");

// W fragments (same layout as R9/R10): g_wf[s*128 + (2*wn+p)*32 + lane]
//   n = (wn*4 + p*2 + jj)*8 + (lane>>2), k = s*16 + (lane&3)*2
__device__ uint4 g_wf[8192];

__global__ void wconv(const float* __restrict__ W)
{
    int id   = blockIdx.x * blockDim.x + threadIdx.x;   // 0..8191
    int lane = id & 31;
    int p    = (id >> 5) & 1;
    int wn   = (id >> 6) & 1;
    int s    = id >> 7;
    int k    = s * 16 + (lane & 3) * 2;
    int j0   = wn * 4 + p * 2;
    uint4 o;
#pragma unroll
    for (int jj = 0; jj < 2; jj++) {
        int n = (j0 + jj) * 8 + (lane >> 2);
        const float* ptr = W + (size_t)n * NEMB + k;
        __half2 h0 = __float22half2_rn(make_float2(ptr[0], ptr[1]));
        __half2 h1 = __float22half2_rn(make_float2(ptr[8], ptr[9]));
        if (jj == 0) { o.x = *(uint32_t*)&h0; o.y = *(uint32_t*)&h1; }
        else         { o.z = *(uint32_t*)&h0; o.w = *(uint32_t*)&h1; }
    }
    g_wf[id] = o;
}

__device__ __forceinline__ void mma16816(float* c,
                                         uint32_t a0, uint32_t a1, uint32_t a2, uint32_t a3,
                                         uint32_t b0, uint32_t b1)
{
    asm volatile(
        "mma.sync.aligned.m16n8k16.row.col.f32.f16.f16.f32 "
        "{%0,%1,%2,%3}, {%4,%5,%6,%7}, {%8,%9}, {%0,%1,%2,%3};"
        : "+f"(c[0]), "+f"(c[1]), "+f"(c[2]), "+f"(c[3])
        : "r"(a0), "r"(a1), "r"(a2), "r"(a3), "r"(b0), "r"(b1));
}

__device__ __forceinline__ void cp16(uint32_t s, const void* g)
{
    asm volatile("cp.async.cg.shared.global [%0], [%1], 16;" :: "r"(s), "l"(g));
}

__device__ __forceinline__ uint32_t packh2(float a, float b)
{
    __half2 h = __float22half2_rn(make_float2(a, b));
    return *(uint32_t*)&h;
}

__shared__ float bias_s[NH];
extern __shared__ char smem[];

__global__ void __launch_bounds__(THREADS)
vproj(const float* __restrict__ x, const float* __restrict__ bv,
      float* __restrict__ out)
{
    const int t   = threadIdx.x;
    const int wid = t >> 5;
    const int lid = t & 31;
    const int kh  = wid >> 2;         // K half: steps 0-3 vs 4-7
    const int wq  = wid & 3;
    const int wm  = wq & 1;           // M slice (16 rows)
    const int wn  = wq >> 1;          // N half (32 cols)
    const int rowbase = blockIdx.x * MT;

    uint4*        wsm = (uint4*)smem;
    unsigned int* xsm = (unsigned int*)(smem + WSM_BYTES);

    if (t < 16) ((float4*)bias_s)[t] = ((const float4*)bv)[t];

    const uint32_t wsm_s = (uint32_t)__cvta_generic_to_shared(wsm);

    // W stage copy: 4 x cp16 per thread per stage
#define WCOPY(stg)                                                          \
    {                                                                       \
        if ((stg) < NCH) {                                                  \
            const uint32_t sb = (uint32_t)((stg) % 3) * (WST_U4 * 16);      \
            _Pragma("unroll")                                               \
            for (int i_ = 0; i_ < 4; i_++)                                  \
                cp16(wsm_s + sb + (uint32_t)(t + THREADS * i_) * 16,        \
                     g_wf + (stg) * WST_U4 + t + THREADS * i_);             \
        }                                                                   \
        asm volatile("cp.async.commit_group;");                             \
    }

    // prologue: 3 W stages in flight
    WCOPY(0) WCOPY(1) WCOPY(2)

    // x loader: row_t = t>>3 (0..31), sub_t = (t>>1)&3, half = t&1
    const int row_t = t >> 3;
    const int sub_t = (t >> 1) & 3;
    const int half  = t & 1;
    const float* xg = x + (size_t)(rowbase + row_t) * NEMB + sub_t * 32 + half * 16;

    float4 xr[4];
#pragma unroll
    for (int q = 0; q < 4; q++) xr[q] = *(const float4*)(xg + q * 4);

#define CONV_ALL(dst)                                                   \
    {                                                                   \
        uint4 u;                                                        \
        u.x = packh2(xr[0].x, xr[0].y);                                 \
        u.y = packh2(xr[2].x, xr[2].y);                                 \
        u.z = packh2(xr[0].z, xr[0].w);                                 \
        u.w = packh2(xr[2].z, xr[2].w);                                 \
        *(uint4*)((dst)) = u;                                           \
        u.x = packh2(xr[1].x, xr[1].y);                                 \
        u.y = packh2(xr[3].x, xr[3].y);                                 \
        u.z = packh2(xr[1].z, xr[1].w);                                 \
        u.w = packh2(xr[3].z, xr[3].w);                                 \
        *(uint4*)((dst) + 4) = u;                                       \
    }

    unsigned int* const xdst = xsm + sub_t * SUBW + row_t * PW + half * 8;
    CONV_ALL(xdst)                       // chunk 0 -> buf 0
    asm volatile("cp.async.wait_group 2;");   // stage 0 landed
    __syncthreads();

    float acc[4][4];
#pragma unroll
    for (int j = 0; j < 4; j++)
#pragma unroll
        for (int e = 0; e < 4; e++) acc[j][e] = 0.0f;

    const int aoffw = (wm * 16 + (lid >> 2)) * PW + (lid & 3) * 2;
    const int wbase = wn * 64 + lid;

#define LOAD_FRAGS(slot, xb, wb, stp)                                   \
    {                                                                   \
        const int sub_ = (stp) >> 1, st_ = (stp) & 1;                   \
        const unsigned int* ap = (xb) + sub_ * SUBW + aoffw + st_ * 8;  \
        av0[slot] = *(const uint2*)ap;                                  \
        av1[slot] = *(const uint2*)(ap + 8 * PW);                       \
        wq0[slot] = (wb)[(stp) * 128 + wbase];                          \
        wq1[slot] = (wb)[(stp) * 128 + wbase + 32];                     \
    }
#define DO_MMAS(slot)                                                   \
    {                                                                   \
        mma16816(acc[0], av0[slot].x, av1[slot].x, av0[slot].y, av1[slot].y, wq0[slot].x, wq0[slot].y); \
        mma16816(acc[1], av0[slot].x, av1[slot].x, av0[slot].y, av1[slot].y, wq0[slot].z, wq0[slot].w); \
        mma16816(acc[2], av0[slot].x, av1[slot].x, av0[slot].y, av1[slot].y, wq1[slot].x, wq1[slot].y); \
        mma16816(acc[3], av0[slot].x, av1[slot].x, av0[slot].y, av1[slot].y, wq1[slot].z, wq1[slot].w); \
    }

#pragma unroll
    for (int c = 0; c < NCH; c++) {
        // next chunk's x LDGs first (latency cover over compute)
        if (c + 1 < NCH) {
#pragma unroll
            for (int q = 0; q < 4; q++)
                xr[q] = *(const float4*)(xg + (c + 1) * KCH + q * 4);
        }

        // compute this warp's 4 k16-steps from x buf c&1 and W stage c%3
        {
            const unsigned int* xb = xsm + (c & 1) * XBUFW;
            const uint4* wb = wsm + (c % 3) * WST_U4;
            uint2 av0[2], av1[2];
            uint4 wq0[2], wq1[2];
            LOAD_FRAGS(0, xb, wb, kh * 4 + 0)
#pragma unroll
            for (int sl = 0; sl < 4; sl++) {
                if (sl < 3) {
                    if ((sl & 1) == 0) LOAD_FRAGS(1, xb, wb, kh * 4 + sl + 1)
                    else               LOAD_FRAGS(0, xb, wb, kh * 4 + sl + 1)
                }
                if ((sl & 1) == 0) DO_MMAS(0)
                else               DO_MMAS(1)
            }
        }

        // convert next x chunk into the other buffer
        if (c + 1 < NCH) CONV_ALL(xsm + ((c + 1) & 1) * XBUFW
                                  + sub_t * SUBW + row_t * PW + half * 8)

        __syncthreads();      // all warps done with stage c & buf c&1
        WCOPY(c + 3)          // refill ring buffer (c+3)%3 == c%3 (always commits)
        asm volatile("cp.async.wait_group 2;");   // stage c+1 ready
    }

    // ---- K-reduction + epilogue ----
    float* red = (float*)xsm;
    const int rbase = (wq * 32 + lid) * 20;
    __syncthreads();
    if (kh == 1) {
#pragma unroll
        for (int j = 0; j < 4; j++)
            *(float4*)(red + rbase + j * 4) = *(float4*)acc[j];
    }
    __syncthreads();
    if (kh == 0) {
        const int orow = rowbase + wm * 16 + (lid >> 2);
#pragma unroll
        for (int j = 0; j < 4; j++) {
            float4 o = *(float4*)(red + rbase + j * 4);
            const int col = wn * 32 + j * 8 + ((lid & 3) << 1);
            const float b0 = bias_s[col], b1 = bias_s[col + 1];
            float2 lo = make_float2(acc[j][0] + o.x + b0, acc[j][1] + o.y + b1);
            float2 hi = make_float2(acc[j][2] + o.z + b0, acc[j][3] + o.w + b1);
            *(float2*)(out + (size_t)orow * NH + col)       = lo;
            *(float2*)(out + (size_t)(orow + 8) * NH + col) = hi;
        }
    }
#undef CONV_ALL
#undef LOAD_FRAGS
#undef DO_MMAS
#undef WCOPY
}

extern "C" void kernel_launch(void* const* d_in, const int* in_sizes, int n_in,
                              void* d_out, int out_size)
{
    const float* x  = (const float*)d_in[0];
    const float* Wv = (const float*)d_in[5];
    const float* bv = (const float*)d_in[6];

    cudaFuncSetAttribute(vproj, cudaFuncAttributeMaxDynamicSharedMemorySize, SMEM_BYTES);
    wconv<<<32, 256>>>(Wv);
    vproj<<<GRID, THREADS, SMEM_BYTES>>>(x, bv, (float*)d_out);
}

// round 13
// speedup vs baseline: 1.5496x; 1.5496x over previous
#include <cuda_runtime.h>
#include <cuda_fp16.h>
#include <cstdint>
#include <cstddef>

// out = x @ Wv^T + bv.  (Reference's softmax rows sum to 1 => its final
// einsum('btu,btj->btj', weights, v) == v + rounding; Q/K/softmax are dead.)
//
// Single-pass fp16 GEMM M=8192, K=1024, N=64 on portable mma.sync m16n8k16.
// R13: x streams via a deep cp.async fp32 ring (3 slots x K128) so the SM
// always has ~40-70KB outstanding -> breaks the measured 1.95 TB/s burst
// ceiling. A-fragments built directly from fp32 smem (LDS.64 + cvt), no fp16
// STS round-trip. W via R12's proven 3-slot fragment ring. 256 CTAs x 256
// threads (8 warps = 2M x 2N x 2K-split), 110.6KB smem -> 2 CTAs/SM.

#define NEMB    1024
#define NH      64
#define MT      32
#define THREADS 256
#define GRID    256              // 8192 / 32
#define NCH     8                // K128 groups
#define XPW     40               // fp32 words per row per K32 stage (pad: LDS.64 conflict-free)
#define XSTG_W  (MT * XPW)       // 1280 words per stage
#define XSLOT_W (4 * XSTG_W)     // 5120 words per slot (K128)
#define XSLOT_B (XSLOT_W * 4)    // 20480 bytes
#define WST_U4  1024             // uint4 per W slot (8 steps * 128)
#define WSM_BYTES (3 * WST_U4 * 16)            // 49152
#define XSM_BYTES (3 * XSLOT_B)                // 61440
#define SMEM_BYTES (WSM_BYTES + XSM_BYTES)     // 110592

static_assert(SMEM_BYTES <= 113664, "2 CTAs/SM");

// W fragments (layout proven R9-R12): g_wf[(g*8+stp)*128 + (wn*2+p)*32 + lane]
__device__ uint4 g_wf[8192];

__global__ void wconv(const float* __restrict__ W)
{
    int id   = blockIdx.x * blockDim.x + threadIdx.x;   // 0..8191
    int lane = id & 31;
    int p    = (id >> 5) & 1;
    int wn   = (id >> 6) & 1;
    int s    = id >> 7;
    int k    = s * 16 + (lane & 3) * 2;
    int j0   = wn * 4 + p * 2;
    uint4 o;
#pragma unroll
    for (int jj = 0; jj < 2; jj++) {
        int n = (j0 + jj) * 8 + (lane >> 2);
        const float* ptr = W + (size_t)n * NEMB + k;
        __half2 h0 = __float22half2_rn(make_float2(ptr[0], ptr[1]));
        __half2 h1 = __float22half2_rn(make_float2(ptr[8], ptr[9]));
        if (jj == 0) { o.x = *(uint32_t*)&h0; o.y = *(uint32_t*)&h1; }
        else         { o.z = *(uint32_t*)&h0; o.w = *(uint32_t*)&h1; }
    }
    g_wf[id] = o;
}

__device__ __forceinline__ void mma16816(float* c,
                                         uint32_t a0, uint32_t a1, uint32_t a2, uint32_t a3,
                                         uint32_t b0, uint32_t b1)
{
    asm volatile(
        "mma.sync.aligned.m16n8k16.row.col.f32.f16.f16.f32 "
        "{%0,%1,%2,%3}, {%4,%5,%6,%7}, {%8,%9}, {%0,%1,%2,%3};"
        : "+f"(c[0]), "+f"(c[1]), "+f"(c[2]), "+f"(c[3])
        : "r"(a0), "r"(a1), "r"(a2), "r"(a3), "r"(b0), "r"(b1));
}

__device__ __forceinline__ void cp16(uint32_t s, const void* g)
{
    asm volatile("cp.async.cg.shared.global [%0], [%1], 16;" :: "r"(s), "l"(g));
}

__device__ __forceinline__ uint32_t packh2(float a, float b)
{
    __half2 h = __float22half2_rn(make_float2(a, b));
    return *(uint32_t*)&h;
}

__shared__ float bias_s[NH];
extern __shared__ char smem[];

__global__ void __launch_bounds__(THREADS)
vproj(const float* __restrict__ x, const float* __restrict__ bv,
      float* __restrict__ out)
{
    const int t   = threadIdx.x;
    const int wid = t >> 5;
    const int lid = t & 31;
    const int kh  = wid >> 2;         // K half: k16-steps kh*4 .. kh*4+3 per group
    const int wq  = wid & 3;
    const int wm  = wq & 1;           // M slice (16 rows)
    const int wn  = wq >> 1;          // N half (32 cols)
    const int rowbase = blockIdx.x * MT;

    uint4* wsm = (uint4*)smem;
    float* xsm = (float*)(smem + WSM_BYTES);

    if (t < 16) ((float4*)bias_s)[t] = ((const float4*)bv)[t];

    const uint32_t wsm_s = (uint32_t)__cvta_generic_to_shared(wsm);
    const uint32_t xsm_s = (uint32_t)__cvta_generic_to_shared(xsm);

    // x producer mapping: row_t = t>>3 (0..31), c16 = t&7 (16B unit in 128B stage-row)
    const int row_t = t >> 3;
    const int c16   = t & 7;
    const float* xrowp = x + (size_t)(rowbase + row_t) * NEMB + c16 * 4;
    const uint32_t xdst_base = xsm_s + (uint32_t)(row_t * XPW * 4 + c16 * 16);

    // one combined commit group per K128: 4 x-stages (4 cp16) + W slot (4 cp16)
#define GCOPY(g)                                                            \
    {                                                                       \
        if ((g) < NCH) {                                                    \
            const uint32_t xslot = (uint32_t)(((g) % 3) * XSLOT_B);         \
            _Pragma("unroll")                                               \
            for (int s_ = 0; s_ < 4; s_++)                                  \
                cp16(xdst_base + xslot + (uint32_t)(s_ * XSTG_W * 4),       \
                     xrowp + (g) * 128 + s_ * 32);                          \
            const uint32_t wslot = (uint32_t)(((g) % 3) * (WST_U4 * 16));   \
            _Pragma("unroll")                                               \
            for (int i_ = 0; i_ < 4; i_++)                                  \
                cp16(wsm_s + wslot + (uint32_t)(t + THREADS * i_) * 16,     \
                     g_wf + (g) * WST_U4 + t + THREADS * i_);               \
        }                                                                   \
        asm volatile("cp.async.commit_group;");                             \
    }

    GCOPY(0) GCOPY(1) GCOPY(2)
    asm volatile("cp.async.wait_group 2;");   // group 0 landed
    __syncthreads();

    float acc[4][4];
#pragma unroll
    for (int j = 0; j < 4; j++)
#pragma unroll
        for (int e = 0; e < 4; e++) acc[j][e] = 0.0f;

    // A fragment: rows a_r, a_r+8; fp32 k-pairs at kp2 and kp2+8 (+ st*16)
    const int a_r  = wm * 16 + (lid >> 2);
    const int kp2  = (lid & 3) * 2;
    const int abase = a_r * XPW + kp2;
    const int wbase = wn * 64 + lid;

    // load + convert fragments for k16-step `stp` of slot `xsl`/`wb`
#define LOAD_FRAGS(slot, xsl, wb, stp)                                      \
    {                                                                       \
        const int stage_ = (stp) >> 1, st_ = (stp) & 1;                     \
        const float* ap = (xsl) + stage_ * XSTG_W + abase + st_ * 16;       \
        float2 f0 = *(const float2*)ap;                                     \
        float2 f1 = *(const float2*)(ap + 8 * XPW);                         \
        float2 f2 = *(const float2*)(ap + 8);                               \
        float2 f3 = *(const float2*)(ap + 8 * XPW + 8);                     \
        a0[slot] = packh2(f0.x, f0.y);                                      \
        a1[slot] = packh2(f1.x, f1.y);                                      \
        a2[slot] = packh2(f2.x, f2.y);                                      \
        a3[slot] = packh2(f3.x, f3.y);                                      \
        wq0[slot] = (wb)[(stp) * 128 + wbase];                              \
        wq1[slot] = (wb)[(stp) * 128 + wbase + 32];                         \
    }
#define DO_MMAS(slot)                                                       \
    {                                                                       \
        mma16816(acc[0], a0[slot], a1[slot], a2[slot], a3[slot], wq0[slot].x, wq0[slot].y); \
        mma16816(acc[1], a0[slot], a1[slot], a2[slot], a3[slot], wq0[slot].z, wq0[slot].w); \
        mma16816(acc[2], a0[slot], a1[slot], a2[slot], a3[slot], wq1[slot].x, wq1[slot].y); \
        mma16816(acc[3], a0[slot], a1[slot], a2[slot], a3[slot], wq1[slot].z, wq1[slot].w); \
    }

#pragma unroll
    for (int c = 0; c < NCH; c++) {
        const float* xsl = xsm + (c % 3) * XSLOT_W;
        const uint4* wb  = wsm + (c % 3) * WST_U4;
        {
            uint32_t a0[2], a1[2], a2[2], a3[2];
            uint4 wq0[2], wq1[2];
            LOAD_FRAGS(0, xsl, wb, kh * 4 + 0)
#pragma unroll
            for (int sl = 0; sl < 4; sl++) {
                if (sl < 3) {
                    if ((sl & 1) == 0) LOAD_FRAGS(1, xsl, wb, kh * 4 + sl + 1)
                    else               LOAD_FRAGS(0, xsl, wb, kh * 4 + sl + 1)
                }
                if ((sl & 1) == 0) DO_MMAS(0)
                else               DO_MMAS(1)
            }
        }
        __syncthreads();          // all warps done reading slot c%3
        GCOPY(c + 3)              // refill the just-freed slot (deep, issue-and-forget)
        asm volatile("cp.async.wait_group 2;");   // group c+1 ready
    }

    // ---- K-split reduction + epilogue ----
    float* red = xsm;
    const int rbase = (wq * 32 + lid) * 20;
    __syncthreads();
    if (kh == 1) {
#pragma unroll
        for (int j = 0; j < 4; j++)
            *(float4*)(red + rbase + j * 4) = *(float4*)acc[j];
    }
    __syncthreads();
    if (kh == 0) {
        const int orow = rowbase + wm * 16 + (lid >> 2);
#pragma unroll
        for (int j = 0; j < 4; j++) {
            float4 o = *(float4*)(red + rbase + j * 4);
            const int col = wn * 32 + j * 8 + ((lid & 3) << 1);
            const float b0 = bias_s[col], b1 = bias_s[col + 1];
            float2 lo = make_float2(acc[j][0] + o.x + b0, acc[j][1] + o.y + b1);
            float2 hi = make_float2(acc[j][2] + o.z + b0, acc[j][3] + o.w + b1);
            *(float2*)(out + (size_t)orow * NH + col)       = lo;
            *(float2*)(out + (size_t)(orow + 8) * NH + col) = hi;
        }
    }
#undef GCOPY
#undef LOAD_FRAGS
#undef DO_MMAS
}

extern "C" void kernel_launch(void* const* d_in, const int* in_sizes, int n_in,
                              void* d_out, int out_size)
{
    const float* x  = (const float*)d_in[0];
    const float* Wv = (const float*)d_in[5];
    const float* bv = (const float*)d_in[6];

    cudaFuncSetAttribute(vproj, cudaFuncAttributeMaxDynamicSharedMemorySize, SMEM_BYTES);
    wconv<<<32, 256>>>(Wv);
    vproj<<<GRID, THREADS, SMEM_BYTES>>>(x, bv, (float*)d_out);
}

// round 14
// speedup vs baseline: 1.7975x; 1.1600x over previous
#include <cuda_runtime.h>
#include <cuda_fp16.h>
#include <cstdint>
#include <cstddef>

// out = x @ Wv^T + bv.  (Reference's softmax rows sum to 1 => its final
// einsum('btu,btj->btj', weights, v) == v + rounding; Q/K/softmax are dead.)
//
// Single-pass fp16 GEMM M=8192, K=1024, N=64 on portable mma.sync m16n8k16.
// R14: W leaves the streaming path — each warp prefetches its next-chunk W
// fragments via 8xLDG.128 from L2-hot g_wf into double-buffered registers.
// x streams through a 5-slot cp.async ring (wait_group 3 -> 4 groups / 64KB
// per CTA in flight). 256 CTAs x 256 threads (8 warps = 2M x 2N x 2K-split),
// 100KB smem -> 2 CTAs/SM.

#define NEMB    1024
#define NH      64
#define MT      32
#define THREADS 256
#define GRID    256              // 8192 / 32
#define NCH     8                // K128 chunks
#define XPW     40               // fp32 words per row per K32 stage (LDS.64 conflict-free)
#define XSTG_W  (MT * XPW)       // 1280 words per stage
#define XSLOT_W (4 * XSTG_W)     // 5120 words per slot (K128)
#define XSLOT_B (XSLOT_W * 4)    // 20480 bytes
#define NSLOT   5
#define SMEM_BYTES (NSLOT * XSLOT_B)   // 102400

static_assert(SMEM_BYTES <= 113000, "2 CTAs/SM");

// W fragments (layout proven R9-R13): g_wf[(c*8+stp)*128 + (wn*2+p)*32 + lane]
__device__ uint4 g_wf[8192];

__global__ void wconv(const float* __restrict__ W)
{
    int id   = blockIdx.x * blockDim.x + threadIdx.x;   // 0..8191
    int lane = id & 31;
    int p    = (id >> 5) & 1;
    int wn   = (id >> 6) & 1;
    int s    = id >> 7;
    int k    = s * 16 + (lane & 3) * 2;
    int j0   = wn * 4 + p * 2;
    uint4 o;
#pragma unroll
    for (int jj = 0; jj < 2; jj++) {
        int n = (j0 + jj) * 8 + (lane >> 2);
        const float* ptr = W + (size_t)n * NEMB + k;
        __half2 h0 = __float22half2_rn(make_float2(ptr[0], ptr[1]));
        __half2 h1 = __float22half2_rn(make_float2(ptr[8], ptr[9]));
        if (jj == 0) { o.x = *(uint32_t*)&h0; o.y = *(uint32_t*)&h1; }
        else         { o.z = *(uint32_t*)&h0; o.w = *(uint32_t*)&h1; }
    }
    g_wf[id] = o;
}

__device__ __forceinline__ void mma16816(float* c,
                                         uint32_t a0, uint32_t a1, uint32_t a2, uint32_t a3,
                                         uint32_t b0, uint32_t b1)
{
    asm volatile(
        "mma.sync.aligned.m16n8k16.row.col.f32.f16.f16.f32 "
        "{%0,%1,%2,%3}, {%4,%5,%6,%7}, {%8,%9}, {%0,%1,%2,%3};"
        : "+f"(c[0]), "+f"(c[1]), "+f"(c[2]), "+f"(c[3])
        : "r"(a0), "r"(a1), "r"(a2), "r"(a3), "r"(b0), "r"(b1));
}

__device__ __forceinline__ void cp16(uint32_t s, const void* g)
{
    asm volatile("cp.async.cg.shared.global [%0], [%1], 16;" :: "r"(s), "l"(g));
}

__device__ __forceinline__ uint32_t packh2(float a, float b)
{
    __half2 h = __float22half2_rn(make_float2(a, b));
    return *(uint32_t*)&h;
}

__shared__ float bias_s[NH];
extern __shared__ char smem[];

__global__ void __launch_bounds__(THREADS)
vproj(const float* __restrict__ x, const float* __restrict__ bv,
      float* __restrict__ out)
{
    const int t   = threadIdx.x;
    const int wid = t >> 5;
    const int lid = t & 31;
    const int kh  = wid >> 2;         // K half: k16-steps kh*4 .. kh*4+3 per chunk
    const int wq  = wid & 3;
    const int wm  = wq & 1;           // M slice (16 rows)
    const int wn  = wq >> 1;          // N half (32 cols)
    const int rowbase = blockIdx.x * MT;

    float* xsm = (float*)smem;

    if (t < 16) ((float4*)bias_s)[t] = ((const float4*)bv)[t];

    const uint32_t xsm_s = (uint32_t)__cvta_generic_to_shared(xsm);

    // x producer mapping: row_t = t>>3 (0..31), c16 = t&7 (16B unit in 512B row-chunk)
    const int row_t = t >> 3;
    const int c16   = t & 7;
    const float* xrowp = x + (size_t)(rowbase + row_t) * NEMB + c16 * 4;
    const uint32_t xdst_base = xsm_s + (uint32_t)(row_t * XPW * 4 + c16 * 16);

#define XCOPY(g)                                                            \
    {                                                                       \
        if ((g) < NCH) {                                                    \
            const uint32_t xslot = (uint32_t)(((g) % NSLOT) * XSLOT_B);     \
            _Pragma("unroll")                                               \
            for (int s_ = 0; s_ < 4; s_++)                                  \
                cp16(xdst_base + xslot + (uint32_t)(s_ * XSTG_W * 4),       \
                     xrowp + (g) * 128 + s_ * 32);                          \
        }                                                                   \
        asm volatile("cp.async.commit_group;");                             \
    }

    const int wbase = wn * 64 + lid;

    // W register prefetch: this warp's 4 steps of chunk cc
#define WLOAD(d0, d1, cc)                                                   \
    {                                                                       \
        if ((cc) < NCH) {                                                   \
            _Pragma("unroll")                                               \
            for (int s_ = 0; s_ < 4; s_++) {                                \
                d0[s_] = g_wf[((cc) * 8 + kh * 4 + s_) * 128 + wbase];      \
                d1[s_] = g_wf[((cc) * 8 + kh * 4 + s_) * 128 + wbase + 32]; \
            }                                                               \
        }                                                                   \
    }

    uint4 wa0[4], wa1[4], wb0[4], wb1[4];
    WLOAD(wa0, wa1, 0)

    XCOPY(0) XCOPY(1) XCOPY(2) XCOPY(3)
    asm volatile("cp.async.wait_group 3;");   // slot 0 ready
    __syncthreads();

    float acc[4][4];
#pragma unroll
    for (int j = 0; j < 4; j++)
#pragma unroll
        for (int e = 0; e < 4; e++) acc[j][e] = 0.0f;

    const int a_r   = wm * 16 + (lid >> 2);
    const int abase = a_r * XPW + (lid & 3) * 2;

    // x fragment load (fp32 smem -> cvt -> fp16 regs) for k16-step `stp`
#define LOAD_XFRAG(slot, xsl, stp)                                          \
    {                                                                       \
        const int stage_ = (stp) >> 1, st_ = (stp) & 1;                     \
        const float* ap = (xsl) + stage_ * XSTG_W + abase + st_ * 16;       \
        float2 f0 = *(const float2*)ap;                                     \
        float2 f1 = *(const float2*)(ap + 8 * XPW);                         \
        float2 f2 = *(const float2*)(ap + 8);                               \
        float2 f3 = *(const float2*)(ap + 8 * XPW + 8);                     \
        a0[slot] = packh2(f0.x, f0.y);                                      \
        a1[slot] = packh2(f1.x, f1.y);                                      \
        a2[slot] = packh2(f2.x, f2.y);                                      \
        a3[slot] = packh2(f3.x, f3.y);                                      \
    }
#define DO_MMAS(slot, W0, W1, s_)                                           \
    {                                                                       \
        mma16816(acc[0], a0[slot], a1[slot], a2[slot], a3[slot], W0[s_].x, W0[s_].y); \
        mma16816(acc[1], a0[slot], a1[slot], a2[slot], a3[slot], W0[s_].z, W0[s_].w); \
        mma16816(acc[2], a0[slot], a1[slot], a2[slot], a3[slot], W1[s_].x, W1[s_].y); \
        mma16816(acc[3], a0[slot], a1[slot], a2[slot], a3[slot], W1[s_].z, W1[s_].w); \
    }

    // one chunk: prefetch next W into (N0,N1), compute from (C0,C1) + x slot
#define CHUNK(c, C0, C1, N0, N1)                                            \
    {                                                                       \
        WLOAD(N0, N1, (c) + 1)                                              \
        const float* xsl = xsm + ((c) % NSLOT) * XSLOT_W;                   \
        uint32_t a0[2], a1[2], a2[2], a3[2];                                \
        LOAD_XFRAG(0, xsl, kh * 4 + 0)                                      \
        LOAD_XFRAG(1, xsl, kh * 4 + 1)                                      \
        DO_MMAS(0, C0, C1, 0)                                               \
        LOAD_XFRAG(0, xsl, kh * 4 + 2)                                      \
        DO_MMAS(1, C0, C1, 1)                                               \
        LOAD_XFRAG(1, xsl, kh * 4 + 3)                                      \
        DO_MMAS(0, C0, C1, 2)                                               \
        DO_MMAS(1, C0, C1, 3)                                               \
        __syncthreads();                                                    \
        XCOPY((c) + 4)                                                      \
        asm volatile("cp.async.wait_group 3;");                             \
    }

    CHUNK(0, wa0, wa1, wb0, wb1)
    CHUNK(1, wb0, wb1, wa0, wa1)
    CHUNK(2, wa0, wa1, wb0, wb1)
    CHUNK(3, wb0, wb1, wa0, wa1)
    CHUNK(4, wa0, wa1, wb0, wb1)
    CHUNK(5, wb0, wb1, wa0, wa1)
    CHUNK(6, wa0, wa1, wb0, wb1)
    CHUNK(7, wb0, wb1, wa0, wa1)

    // ---- K-split reduction + epilogue ----
    float* red = xsm;
    const int rbase = (wq * 32 + lid) * 20;
    __syncthreads();
    if (kh == 1) {
#pragma unroll
        for (int j = 0; j < 4; j++)
            *(float4*)(red + rbase + j * 4) = *(float4*)acc[j];
    }
    __syncthreads();
    if (kh == 0) {
        const int orow = rowbase + wm * 16 + (lid >> 2);
#pragma unroll
        for (int j = 0; j < 4; j++) {
            float4 o = *(float4*)(red + rbase + j * 4);
            const int col = wn * 32 + j * 8 + ((lid & 3) << 1);
            const float b0 = bias_s[col], b1 = bias_s[col + 1];
            float2 lo = make_float2(acc[j][0] + o.x + b0, acc[j][1] + o.y + b1);
            float2 hi = make_float2(acc[j][2] + o.z + b0, acc[j][3] + o.w + b1);
            *(float2*)(out + (size_t)orow * NH + col)       = lo;
            *(float2*)(out + (size_t)(orow + 8) * NH + col) = hi;
        }
    }
#undef XCOPY
#undef WLOAD
#undef LOAD_XFRAG
#undef DO_MMAS
#undef CHUNK
}

extern "C" void kernel_launch(void* const* d_in, const int* in_sizes, int n_in,
                              void* d_out, int out_size)
{
    const float* x  = (const float*)d_in[0];
    const float* Wv = (const float*)d_in[5];
    const float* bv = (const float*)d_in[6];

    cudaFuncSetAttribute(vproj, cudaFuncAttributeMaxDynamicSharedMemorySize, SMEM_BYTES);
    wconv<<<32, 256>>>(Wv);
    vproj<<<GRID, THREADS, SMEM_BYTES>>>(x, bv, (float*)d_out);
}